// round 7
// baseline (speedup 1.0000x reference)
#include <cuda_runtime.h>

// Memory_9835475108444: Hebbian fast-weight scan, low-rank reformulation (exact):
//   A_t = (1-d)^t A_0 + sum_{s<t} (1-d)^{t-1-s} x_s p_s^T
// Kernel 1 (grid 4x256): stream A_0 once at the HBM wall; zero chunks set a
//   flag, nonzero chunks compute g_t = A_0 @ x_t into scratch (general path).
// Kernel 2 (grid 256): rank-16 recurrence, ONE barrier per step:
//   critical dot p_{t-1}.x_t from registers (1 tree/warp), stale dots (s<=t-2)
//   via smem p with >=1 step of visibility slack; parity double-buffered qs/wp.

#define BB 256
#define MM 256
#define TT 16
#define NCHUNK 4
#define ROWS_PER_CHUNK (MM / NCHUNK)   // 64

__device__ float g_scratch[BB * (TT + 1) * MM];
__device__ int   g_flags[BB * NCHUNK];   // 1 = chunk nonzero, 0 = zero

__device__ __forceinline__ unsigned f4or(float4 v) {
    return __float_as_uint(v.x) | __float_as_uint(v.y) |
           __float_as_uint(v.z) | __float_as_uint(v.w);
}

__device__ __forceinline__ float tree_sum(float v) {
    #pragma unroll
    for (int off = 16; off > 0; off >>= 1)
        v += __shfl_down_sync(0xffffffffu, v, off);
    return v;
}

// ---------------- kernel 1: stream A_0 (max MLP), zero fast path ---------------
__global__ __launch_bounds__(MM) void scan_gemv_kernel(
    const float* __restrict__ A0,     // (B, M, M)
    const float* __restrict__ xs,     // (T, B, M)
    const float* __restrict__ xq)     // (B, M)
{
    __shared__ float sx[TT + 1][MM + 1];

    const int c    = blockIdx.x;
    const int b    = blockIdx.y;
    const int tid  = threadIdx.x;
    const int lane = tid & 31;
    const int wid  = tid >> 5;

    const float4* __restrict__ p =
        reinterpret_cast<const float4*>(A0) + (size_t)b * (MM * MM / 4)
                                            + (size_t)c * (ROWS_PER_CHUNK * MM / 4);

    unsigned nz = 0u;
    #pragma unroll
    for (int k = 0; k < 16; k++)
        nz |= f4or(p[tid + k * MM]);       // 16 independent LDG.128

    if (!__syncthreads_or((int)(nz != 0u))) {
        if (tid == 0) g_flags[b * NCHUNK + c] = 0;
        return;
    }

    // general path (arbitrary A_0): chunk hot in cache; warp-per-row 17-dots
    #pragma unroll
    for (int t = 0; t < TT; t++)
        sx[t][tid] = xs[(size_t)t * BB * MM + (size_t)b * MM + tid];
    sx[TT][tid] = xq[(size_t)b * MM + tid];
    __syncthreads();

    float* __restrict__ gb = g_scratch + (size_t)b * (TT + 1) * MM;

    #pragma unroll
    for (int rr = 0; rr < ROWS_PER_CHUNK / 8; rr++) {
        const int row_local = wid * (ROWS_PER_CHUNK / 8) + rr;
        const float4* ar = p + row_local * (MM / 4);
        float4 a0 = ar[lane];
        float4 a1 = ar[lane + 32];
        float acc[TT + 1];
        #pragma unroll
        for (int t = 0; t <= TT; t++) acc[t] = 0.f;
        const int j0 = lane * 4, j1 = (lane + 32) * 4;
        #pragma unroll
        for (int t = 0; t <= TT; t++) {
            acc[t] += a0.x * sx[t][j0]     + a0.y * sx[t][j0 + 1]
                    + a0.z * sx[t][j0 + 2] + a0.w * sx[t][j0 + 3];
            acc[t] += a1.x * sx[t][j1]     + a1.y * sx[t][j1 + 1]
                    + a1.z * sx[t][j1 + 2] + a1.w * sx[t][j1 + 3];
        }
        #pragma unroll
        for (int t = 0; t <= TT; t++) acc[t] = tree_sum(acc[t]);
        if (lane == 0) {
            int row = c * ROWS_PER_CHUNK + row_local;
            #pragma unroll
            for (int t = 0; t <= TT; t++) gb[t * MM + row] = acc[t];
        }
    }
    if (tid == 0) g_flags[b * NCHUNK + c] = 1;
}

// ---------- kernel 2: rank-16 recurrence, one barrier per step -----------------
__global__ __launch_bounds__(MM, 2) void recurrence_kernel(
    const float* __restrict__ xs,
    const float* __restrict__ xq,
    const float* __restrict__ pdecay,
    const float* __restrict__ plearn,
    const float* __restrict__ plearn2,
    float* __restrict__ out)
{
    __shared__ float sxm[TT + 1][MM];   // x_0..x_15, x_query
    __shared__ float psm[TT][MM];       // p_s vectors (stale-dot source)
    __shared__ float qs[2][TT];         // parity-buffered stale dots
    __shared__ float wp[2][8];          // parity-buffered critical-dot partials

    const int b    = blockIdx.x;
    const int tid  = threadIdx.x;
    const int lane = tid & 31;
    const int wid  = tid >> 5;

    float xr[TT + 1];
    #pragma unroll
    for (int t = 0; t < TT; t++) {
        xr[t] = xs[(size_t)t * BB * MM + (size_t)b * MM + tid];
        sxm[t][tid] = xr[t];
    }
    xr[TT] = xq[(size_t)b * MM + tid];
    sxm[TT][tid] = xr[TT];

    float gr[TT + 1];
    if (g_flags[b * NCHUNK + (tid >> 6)]) {
        const float* __restrict__ gb = g_scratch + (size_t)b * (TT + 1) * MM;
        #pragma unroll
        for (int t = 0; t <= TT; t++) gr[t] = gb[t * MM + tid];
    } else {
        #pragma unroll
        for (int t = 0; t <= TT; t++) gr[t] = 0.f;
    }

    const float decay  = pdecay[0];
    const float learn  = plearn[0];
    const float learn2 = plearn2[0];
    const float omd    = 1.0f - decay;

    float omdp[TT];                      // omd^k
    omdp[0] = 1.0f;
    #pragma unroll
    for (int k = 1; k < TT; k++) omdp[k] = omdp[k - 1] * omd;
    const float pwT = omdp[TT - 1] * omd;   // omd^16

    float pw = 1.0f;                     // (1-d)^t
    float pr_prev = 0.0f;                // p_{t-1}[tid]

    // Visibility schedule (one bar per step, at phase 3 of steps t>=1):
    //   psm[s] STS at phase4(s)  -> bar(s+1) -> first LDS at phase2(s+2).  OK
    //   qs/wp parity buffers: writers use (t&1); readers of step t-1 use other.
    #pragma unroll
    for (int t = 0; t < TT; t++) {
        // phase 1: critical dot q_{t,t-1} = p_{t-1} . x_t, pure registers
        if (t >= 1) {
            float v = tree_sum(pr_prev * xr[t]);
            if (lane == 0) wp[t & 1][wid] = v;
        }
        // phase 2: stale dots q_{t,s} = p_s . x_t for s <= t-2 (<=2 per warp)
        if (t >= 2) {
            const float4* xv = reinterpret_cast<const float4*>(sxm[t]);
            float4 b0 = xv[lane];
            float4 b1 = xv[lane + 32];
            #pragma unroll
            for (int pass = 0; pass < 2; pass++) {
                int s = wid + pass * 8;
                if (s <= t - 2) {
                    const float4* pv = reinterpret_cast<const float4*>(psm[s]);
                    float4 a0 = pv[lane];
                    float4 a1 = pv[lane + 32];
                    float part = a0.x * b0.x + a0.y * b0.y
                               + a0.z * b0.z + a0.w * b0.w
                               + a1.x * b1.x + a1.y * b1.y
                               + a1.z * b1.z + a1.w * b1.w;
                    part = tree_sum(part);
                    if (lane == 0) qs[t & 1][s] = part;
                }
            }
        }
        // phase 3: single barrier
        if (t >= 1) __syncthreads();

        // phase 4: assemble and advance
        float ax = pw * gr[t];
        #pragma unroll
        for (int s = 0; s <= t - 2; s++)
            ax += omdp[t - 1 - s] * qs[t & 1][s] * xr[s];
        if (t >= 1) {
            float4 lo = *reinterpret_cast<const float4*>(&wp[t & 1][0]);
            float4 hi = *reinterpret_cast<const float4*>(&wp[t & 1][4]);
            float qc = ((lo.x + lo.y) + (lo.z + lo.w)) +
                       ((hi.x + hi.y) + (hi.z + hi.w));
            ax += qc * xr[t - 1];        // omd^0 coefficient
        }
        float v = learn2 * xr[t] + ax;
        float pt = learn * fminf(fmaxf(v, 0.f), 6.f);
        psm[t][tid] = pt;
        pr_prev = pt;
        pw *= omd;
    }

    // ---- epilogue: out = relu6(A_16 @ x_query); s=15 via registers ----
    {
        float v = tree_sum(pr_prev * xr[TT]);
        if (lane == 0) wp[0][wid] = v;

        const float4* xv = reinterpret_cast<const float4*>(sxm[TT]);
        float4 b0 = xv[lane];
        float4 b1 = xv[lane + 32];
        #pragma unroll
        for (int pass = 0; pass < 2; pass++) {
            int s = wid + pass * 8;
            if (s <= TT - 2) {           // s = 0..14 (psm[14] visible via bar(15))
                const float4* pv = reinterpret_cast<const float4*>(psm[s]);
                float4 a0 = pv[lane];
                float4 a1 = pv[lane + 32];
                float part = a0.x * b0.x + a0.y * b0.y
                           + a0.z * b0.z + a0.w * b0.w
                           + a1.x * b1.x + a1.y * b1.y
                           + a1.z * b1.z + a1.w * b1.w;
                part = tree_sum(part);
                if (lane == 0) qs[0][s] = part;
            }
        }
        __syncthreads();
    }

    float ax = pwT * gr[TT];
    #pragma unroll
    for (int s = 0; s <= TT - 2; s++)
        ax += omdp[TT - 1 - s] * qs[0][s] * xr[s];
    {
        float4 lo = *reinterpret_cast<const float4*>(&wp[0][0]);
        float4 hi = *reinterpret_cast<const float4*>(&wp[0][4]);
        float qc = ((lo.x + lo.y) + (lo.z + lo.w)) +
                   ((hi.x + hi.y) + (hi.z + hi.w));
        ax += qc * xr[TT - 1];
    }
    out[(size_t)b * MM + tid] = fminf(fmaxf(ax, 0.f), 6.f);
}

extern "C" void kernel_launch(void* const* d_in, const int* in_sizes, int n_in,
                              void* d_out, int out_size) {
    const float* A0     = (const float*)d_in[0];
    const float* xs     = (const float*)d_in[1];
    const float* xq     = (const float*)d_in[2];
    const float* decay  = (const float*)d_in[3];
    const float* learn  = (const float*)d_in[4];
    const float* learn2 = (const float*)d_in[5];
    float* out = (float*)d_out;

    dim3 g1(NCHUNK, BB);
    scan_gemv_kernel<<<g1, MM>>>(A0, xs, xq);
    recurrence_kernel<<<BB, MM>>>(xs, xq, decay, learn, learn2, out);
}

// round 8
// speedup vs baseline: 1.0327x; 1.0327x over previous
#include <cuda_runtime.h>

// Memory_9835475108444: Hebbian fast-weight scan, low-rank reformulation (exact):
//   A_t = (1-d)^t A_0 + sum_{s<t} (1-d)^{t-1-s} x_s p_s^T
// Kernel 1 (grid 4x256): stream A_0 once at the HBM wall; zero chunks set a
//   flag, nonzero chunks compute g_t = A_0 @ x_t into scratch (general path).
// Kernel 2 (grid 256 x 32): ONE WARP PER BATCH. p vectors fully register
//   resident (lane owns 8 elements), dots via shfl_xor butterflies, x re-reads
//   from L1-cached global. No shared memory, no barriers.

#define BB 256
#define MM 256
#define TT 16
#define NCHUNK 4
#define ROWS_PER_CHUNK (MM / NCHUNK)   // 64

__device__ float g_scratch[BB * (TT + 1) * MM];
__device__ int   g_flags[BB * NCHUNK];   // 1 = chunk nonzero, 0 = zero

__device__ __forceinline__ unsigned f4or(float4 v) {
    return __float_as_uint(v.x) | __float_as_uint(v.y) |
           __float_as_uint(v.z) | __float_as_uint(v.w);
}

__device__ __forceinline__ float tree_sum(float v) {      // result in lane 0
    #pragma unroll
    for (int off = 16; off > 0; off >>= 1)
        v += __shfl_down_sync(0xffffffffu, v, off);
    return v;
}

__device__ __forceinline__ float bfly_sum(float v) {      // result in ALL lanes
    #pragma unroll
    for (int off = 16; off > 0; off >>= 1)
        v += __shfl_xor_sync(0xffffffffu, v, off);
    return v;
}

// ---------------- kernel 1: stream A_0 (max MLP), zero fast path ---------------
__global__ __launch_bounds__(MM) void scan_gemv_kernel(
    const float* __restrict__ A0,     // (B, M, M)
    const float* __restrict__ xs,     // (T, B, M)
    const float* __restrict__ xq)     // (B, M)
{
    __shared__ float sx[TT + 1][MM + 1];

    const int c    = blockIdx.x;
    const int b    = blockIdx.y;
    const int tid  = threadIdx.x;
    const int lane = tid & 31;
    const int wid  = tid >> 5;

    const float4* __restrict__ p =
        reinterpret_cast<const float4*>(A0) + (size_t)b * (MM * MM / 4)
                                            + (size_t)c * (ROWS_PER_CHUNK * MM / 4);

    unsigned nz = 0u;
    #pragma unroll
    for (int k = 0; k < 16; k++)
        nz |= f4or(p[tid + k * MM]);       // 16 independent LDG.128

    if (!__syncthreads_or((int)(nz != 0u))) {
        if (tid == 0) g_flags[b * NCHUNK + c] = 0;
        return;
    }

    // general path (arbitrary A_0): chunk hot in cache; warp-per-row 17-dots
    #pragma unroll
    for (int t = 0; t < TT; t++)
        sx[t][tid] = xs[(size_t)t * BB * MM + (size_t)b * MM + tid];
    sx[TT][tid] = xq[(size_t)b * MM + tid];
    __syncthreads();

    float* __restrict__ gb = g_scratch + (size_t)b * (TT + 1) * MM;

    #pragma unroll
    for (int rr = 0; rr < ROWS_PER_CHUNK / 8; rr++) {
        const int row_local = wid * (ROWS_PER_CHUNK / 8) + rr;
        const float4* ar = p + row_local * (MM / 4);
        float4 a0 = ar[lane];
        float4 a1 = ar[lane + 32];
        float acc[TT + 1];
        #pragma unroll
        for (int t = 0; t <= TT; t++) acc[t] = 0.f;
        const int j0 = lane * 4, j1 = (lane + 32) * 4;
        #pragma unroll
        for (int t = 0; t <= TT; t++) {
            acc[t] += a0.x * sx[t][j0]     + a0.y * sx[t][j0 + 1]
                    + a0.z * sx[t][j0 + 2] + a0.w * sx[t][j0 + 3];
            acc[t] += a1.x * sx[t][j1]     + a1.y * sx[t][j1 + 1]
                    + a1.z * sx[t][j1 + 2] + a1.w * sx[t][j1 + 3];
        }
        #pragma unroll
        for (int t = 0; t <= TT; t++) acc[t] = tree_sum(acc[t]);
        if (lane == 0) {
            int row = c * ROWS_PER_CHUNK + row_local;
            #pragma unroll
            for (int t = 0; t <= TT; t++) gb[t * MM + row] = acc[t];
        }
    }
    if (tid == 0) g_flags[b * NCHUNK + c] = 1;
}

// -------- kernel 2: warp-per-batch recurrence (no smem, no barriers) -----------
__global__ __launch_bounds__(32) void recurrence_kernel(
    const float* __restrict__ xs,
    const float* __restrict__ xq,
    const float* __restrict__ pdecay,
    const float* __restrict__ plearn,
    const float* __restrict__ plearn2,
    float* __restrict__ out)
{
    const int b    = blockIdx.x;
    const int lane = threadIdx.x;     // lane owns elements [8*lane, 8*lane+8)

    const float decay  = pdecay[0];
    const float learn  = plearn[0];
    const float learn2 = plearn2[0];
    const float omd    = 1.0f - decay;

    float omdp[TT];                   // omd^k
    omdp[0] = 1.0f;
    #pragma unroll
    for (int k = 1; k < TT; k++) omdp[k] = omdp[k - 1] * omd;
    const float pwT = omdp[TT - 1] * omd;   // omd^16

    // own-slice accessors (float4 indices 2*lane, 2*lane+1 of each 256-vector)
    #define XSLICE(base) { \
        const float4* _p = reinterpret_cast<const float4*>(base) + 2 * lane; \
        v0 = _p[0]; v1 = _p[1]; }

    const int flag = g_flags[b * NCHUNK + (lane >> 3)];
    const float* __restrict__ gb = g_scratch + (size_t)b * (TT + 1) * MM + lane * 8;

    float pr[TT][8];                  // register-resident p vectors
    float xt[8];                      // current x_t own slice
    {
        float4 v0, v1;
        XSLICE(xs + (size_t)b * MM);  // x_0
        xt[0]=v0.x; xt[1]=v0.y; xt[2]=v0.z; xt[3]=v0.w;
        xt[4]=v1.x; xt[5]=v1.y; xt[6]=v1.z; xt[7]=v1.w;
    }

    float pw = 1.0f;                  // (1-d)^t

    #pragma unroll
    for (int t = 0; t < TT; t++) {
        // prefetch next x (x_{t+1}, or x_query on the last step)
        float4 n0, n1;
        {
            const float* nsrc = (t + 1 < TT)
                ? xs + ((size_t)(t + 1) * BB + b) * MM
                : xq + (size_t)b * MM;
            const float4* _p = reinterpret_cast<const float4*>(nsrc) + 2 * lane;
            n0 = _p[0]; n1 = _p[1];
        }

        // ax init with A_0 term (zero fast path: no loads at all)
        float ax[8];
        if (flag) {
            const float4* gp = reinterpret_cast<const float4*>(gb + t * MM);
            float4 g0 = gp[0], g1 = gp[1];
            ax[0]=pw*g0.x; ax[1]=pw*g0.y; ax[2]=pw*g0.z; ax[3]=pw*g0.w;
            ax[4]=pw*g1.x; ax[5]=pw*g1.y; ax[6]=pw*g1.z; ax[7]=pw*g1.w;
        } else {
            #pragma unroll
            for (int e = 0; e < 8; e++) ax[e] = 0.f;
        }

        // dots + axpy, s = t-1 first (its butterfly is the critical path)
        #pragma unroll
        for (int k = 0; k < TT; k++) {
            const int s = t - 1 - k;
            if (s >= 0) {
                float part = pr[s][0]*xt[0] + pr[s][1]*xt[1]
                           + pr[s][2]*xt[2] + pr[s][3]*xt[3]
                           + pr[s][4]*xt[4] + pr[s][5]*xt[5]
                           + pr[s][6]*xt[6] + pr[s][7]*xt[7];
                part = bfly_sum(part);                  // q_{t,s} in all lanes
                const float w = omdp[t - 1 - s] * part;
                float4 v0, v1;
                XSLICE(xs + ((size_t)s * BB + b) * MM); // L1 hit after 1st touch
                ax[0]+=w*v0.x; ax[1]+=w*v0.y; ax[2]+=w*v0.z; ax[3]+=w*v0.w;
                ax[4]+=w*v1.x; ax[5]+=w*v1.y; ax[6]+=w*v1.z; ax[7]+=w*v1.w;
            }
        }

        // p_t = learn * relu6(learn2 * x_t + ax)
        #pragma unroll
        for (int e = 0; e < 8; e++) {
            float v = learn2 * xt[e] + ax[e];
            pr[t][e] = learn * fminf(fmaxf(v, 0.f), 6.f);
        }
        pw *= omd;

        xt[0]=n0.x; xt[1]=n0.y; xt[2]=n0.z; xt[3]=n0.w;
        xt[4]=n1.x; xt[5]=n1.y; xt[6]=n1.z; xt[7]=n1.w;
    }

    // ---- epilogue: xt == x_query; out = relu6(A_16 @ x_query) ----
    float ax[8];
    if (flag) {
        const float4* gp = reinterpret_cast<const float4*>(gb + TT * MM);
        float4 g0 = gp[0], g1 = gp[1];
        ax[0]=pwT*g0.x; ax[1]=pwT*g0.y; ax[2]=pwT*g0.z; ax[3]=pwT*g0.w;
        ax[4]=pwT*g1.x; ax[5]=pwT*g1.y; ax[6]=pwT*g1.z; ax[7]=pwT*g1.w;
    } else {
        #pragma unroll
        for (int e = 0; e < 8; e++) ax[e] = 0.f;
    }

    #pragma unroll
    for (int k = 0; k < TT; k++) {
        const int s = TT - 1 - k;
        float part = pr[s][0]*xt[0] + pr[s][1]*xt[1]
                   + pr[s][2]*xt[2] + pr[s][3]*xt[3]
                   + pr[s][4]*xt[4] + pr[s][5]*xt[5]
                   + pr[s][6]*xt[6] + pr[s][7]*xt[7];
        part = bfly_sum(part);
        const float w = omdp[TT - 1 - s] * part;
        float4 v0, v1;
        XSLICE(xs + ((size_t)s * BB + b) * MM);
        ax[0]+=w*v0.x; ax[1]+=w*v0.y; ax[2]+=w*v0.z; ax[3]+=w*v0.w;
        ax[4]+=w*v1.x; ax[5]+=w*v1.y; ax[6]+=w*v1.z; ax[7]+=w*v1.w;
    }

    float4 o0, o1;
    o0.x = fminf(fmaxf(ax[0], 0.f), 6.f);
    o0.y = fminf(fmaxf(ax[1], 0.f), 6.f);
    o0.z = fminf(fmaxf(ax[2], 0.f), 6.f);
    o0.w = fminf(fmaxf(ax[3], 0.f), 6.f);
    o1.x = fminf(fmaxf(ax[4], 0.f), 6.f);
    o1.y = fminf(fmaxf(ax[5], 0.f), 6.f);
    o1.z = fminf(fmaxf(ax[6], 0.f), 6.f);
    o1.w = fminf(fmaxf(ax[7], 0.f), 6.f);
    float4* op = reinterpret_cast<float4*>(out + (size_t)b * MM) + 2 * lane;
    op[0] = o0;
    op[1] = o1;
    #undef XSLICE
}

extern "C" void kernel_launch(void* const* d_in, const int* in_sizes, int n_in,
                              void* d_out, int out_size) {
    const float* A0     = (const float*)d_in[0];
    const float* xs     = (const float*)d_in[1];
    const float* xq     = (const float*)d_in[2];
    const float* decay  = (const float*)d_in[3];
    const float* learn  = (const float*)d_in[4];
    const float* learn2 = (const float*)d_in[5];
    float* out = (float*)d_out;

    dim3 g1(NCHUNK, BB);
    scan_gemv_kernel<<<g1, MM>>>(A0, xs, xq);
    recurrence_kernel<<<BB, 32>>>(xs, xq, decay, learn, learn2, out);
}